// round 4
// baseline (speedup 1.0000x reference)
#include <cuda_runtime.h>
#include <cuda_bf16.h>
#include <cstdint>
#include <cstddef>

// ============================================================================
// KMeansLoss on GB300 via legacy mma.sync (HMMA bf16) — harness ptxas target
// is sm_103 (no 'a'); tcgen05 unavailable.
//
// loss = ALPHA * mean_n sqrt(max( xsq[n] + min_k( csq[k] - 2*dot(x_n,c_k) ), 0))
//
// Kernel 0 (16 CTAs): centers fp32 -> bf16 mma-fragment order + exact csq.
// Kernel 1 (512 CTAs x 128 thr, 3 CTAs/SM): warp owns 32 rows; A fragments
//   loaded DIRECTLY gmem->regs (128 regs) with fused exact fp32 xsq (regs);
//   16 N-chunks of 32 centers, cp.async double-buffered B, single barrier
//   per chunk, acc split in 2 nb-groups (16 live accs) to fit 170 regs;
//   fold (csq - 2*dot) into running per-row min; deterministic last-CTA
//   reduction writes the scalar.
// ============================================================================

namespace km {

constexpr int BATCH = 65536;
constexpr int KC    = 512;
constexpr int DIM   = 256;
constexpr float ALPHA = 0.05f;

constexpr int M_CTA    = 128;
constexpr int NUM_CTAS = BATCH / M_CTA;     // 512
constexpr int NCH      = 32;                // centers per chunk
constexpr int NCHUNKS  = KC / NCH;          // 16
constexpr int CHUNK_BYTES = NCH * DIM * 2;  // 16384

// ---- dynamic smem layout ----
constexpr int SM_CSQ = 0;                   // 512 f = 2048 B
constexpr int SM_RED = 2048;                // 4 f
constexpr int SM_BB  = 4096;                // 2 x 16 KB B buffers
constexpr int SMEM_TOTAL = SM_BB + 2 * CHUNK_BYTES;   // 36864

// B fragments: [nbg(64)][ks(16)][lane(32)] x uint2 (b0 = k pair, b1 = k+8 pair)
__device__ uint2 g_Bfrag[(KC / 8) * 16 * 32];
__device__ float g_csq[KC];
__device__ float g_partials[NUM_CTAS];
__device__ unsigned int g_done;

// ---------------------------- helpers ---------------------------------------
__device__ __forceinline__ uint32_t pk_bf16x2(float lo, float hi) {
    uint32_t r;
    asm("cvt.rn.bf16x2.f32 %0, %1, %2;" : "=r"(r) : "f"(hi), "f"(lo));
    return r;
}
__device__ __forceinline__ void mma16816(float c[4], const uint32_t a[4],
                                         uint32_t b0, uint32_t b1) {
    asm volatile(
        "mma.sync.aligned.m16n8k16.row.col.f32.bf16.bf16.f32 "
        "{%0,%1,%2,%3}, {%4,%5,%6,%7}, {%8,%9}, {%0,%1,%2,%3};"
        : "+f"(c[0]), "+f"(c[1]), "+f"(c[2]), "+f"(c[3])
        : "r"(a[0]), "r"(a[1]), "r"(a[2]), "r"(a[3]), "r"(b0), "r"(b1));
}
__device__ __forceinline__ uint32_t smem_u32(const void* p) {
    return (uint32_t)__cvta_generic_to_shared(p);
}
__device__ __forceinline__ void cp16(uint32_t sdst, const void* gsrc) {
    asm volatile("cp.async.cg.shared.global [%0], [%1], 16;"
                 :: "r"(sdst), "l"(gsrc) : "memory");
}
__device__ __forceinline__ void cp_commit() {
    asm volatile("cp.async.commit_group;" ::: "memory");
}
template <int N>
__device__ __forceinline__ void cp_wait() {
    asm volatile("cp.async.wait_group %0;" :: "n"(N) : "memory");
}

// ------------------------- kernel 0: center convert -------------------------
__global__ void __launch_bounds__(128) convert_centers(const float* __restrict__ ctr) {
    const int tid = threadIdx.x;
    const int w   = tid >> 5;
    const int l   = tid & 31;
    const int nbg = blockIdx.x * 4 + w;         // 0..63
    const int n   = nbg * 8 + (l >> 2);
    const float* row = ctr + (size_t)n * DIM;
    float cs = 0.0f;
    #pragma unroll
    for (int ks = 0; ks < 16; ++ks) {
        const int k0 = ks * 16 + 2 * (l & 3);
        const float2 v0 = *reinterpret_cast<const float2*>(row + k0);
        const float2 v1 = *reinterpret_cast<const float2*>(row + k0 + 8);
        cs = fmaf(v0.x, v0.x, cs); cs = fmaf(v0.y, v0.y, cs);
        cs = fmaf(v1.x, v1.x, cs); cs = fmaf(v1.y, v1.y, cs);
        uint2 u;
        u.x = pk_bf16x2(v0.x, v0.y);
        u.y = pk_bf16x2(v1.x, v1.y);
        g_Bfrag[(nbg * 16 + ks) * 32 + l] = u;
    }
    cs += __shfl_xor_sync(0xFFFFFFFFu, cs, 1);
    cs += __shfl_xor_sync(0xFFFFFFFFu, cs, 2);
    if ((l & 3) == 0) g_csq[n] = cs;
}

// ------------------------- kernel 1: main GEMM+min --------------------------
__global__ void __launch_bounds__(128, 3)
kmeans_main(const float* __restrict__ emb, float* __restrict__ out) {
    extern __shared__ char smem[];
    const int tid = threadIdx.x;
    const int w   = tid >> 5;        // warp 0..3
    const int l   = tid & 31;
    const int m0  = blockIdx.x * M_CTA;
    float* csq_s = reinterpret_cast<float*>(smem + SM_CSQ);
    float* red_s = reinterpret_cast<float*>(smem + SM_RED);
    const uint32_t sbase = smem_u32(smem);

    // ---- prefetch csq + B chunk 0 (overlaps the whole A prologue) ----
    cp16(sbase + SM_CSQ + tid * 16,
         reinterpret_cast<const char*>(g_csq) + tid * 16);
    {
        const char* src = reinterpret_cast<const char*>(g_Bfrag);
        #pragma unroll
        for (int i = 0; i < 8; ++i) {
            const int off = (i * 128 + tid) * 16;
            cp16(sbase + SM_BB + off, src + off);
        }
    }
    cp_commit();

    // ---- A prologue: direct gmem -> register fragments, fused exact xsq ----
    // warp rows: r(mt) = w*32 + mt*16 + (l>>2), and r+8.
    uint32_t a[2][16][4];
    float xs[2][2];
    xs[0][0] = 0.0f; xs[0][1] = 0.0f; xs[1][0] = 0.0f; xs[1][1] = 0.0f;
    {
        const float* base = emb + (size_t)(m0 + w * 32 + (l >> 2)) * DIM + 2 * (l & 3);
        #pragma unroll
        for (int mt = 0; mt < 2; ++mt) {
            const float* p0 = base + (size_t)(mt * 16) * DIM;
            const float* p8 = p0 + (size_t)8 * DIM;
            #pragma unroll
            for (int ks = 0; ks < 16; ++ks) {
                const float2 v00 = *reinterpret_cast<const float2*>(p0 + ks * 16);
                const float2 v01 = *reinterpret_cast<const float2*>(p0 + ks * 16 + 8);
                const float2 v10 = *reinterpret_cast<const float2*>(p8 + ks * 16);
                const float2 v11 = *reinterpret_cast<const float2*>(p8 + ks * 16 + 8);
                xs[mt][0] = fmaf(v00.x, v00.x, xs[mt][0]);
                xs[mt][0] = fmaf(v00.y, v00.y, xs[mt][0]);
                xs[mt][0] = fmaf(v01.x, v01.x, xs[mt][0]);
                xs[mt][0] = fmaf(v01.y, v01.y, xs[mt][0]);
                xs[mt][1] = fmaf(v10.x, v10.x, xs[mt][1]);
                xs[mt][1] = fmaf(v10.y, v10.y, xs[mt][1]);
                xs[mt][1] = fmaf(v11.x, v11.x, xs[mt][1]);
                xs[mt][1] = fmaf(v11.y, v11.y, xs[mt][1]);
                a[mt][ks][0] = pk_bf16x2(v00.x, v00.y);
                a[mt][ks][1] = pk_bf16x2(v10.x, v10.y);
                a[mt][ks][2] = pk_bf16x2(v01.x, v01.y);
                a[mt][ks][3] = pk_bf16x2(v11.x, v11.y);
            }
        }
    }
    // quad-reduce xsq (full row sums; all 4 lanes of a quad hold the value)
    #pragma unroll
    for (int mt = 0; mt < 2; ++mt) {
        #pragma unroll
        for (int h = 0; h < 2; ++h) {
            xs[mt][h] += __shfl_xor_sync(0xFFFFFFFFu, xs[mt][h], 1);
            xs[mt][h] += __shfl_xor_sync(0xFFFFFFFFu, xs[mt][h], 2);
        }
    }

    float minv[2][2];
    minv[0][0] = 3.4e38f; minv[0][1] = 3.4e38f;
    minv[1][0] = 3.4e38f; minv[1][1] = 3.4e38f;

    // ---- mainloop: 16 chunks of 32 centers, ONE barrier per chunk ----
    #pragma unroll 1
    for (int ck = 0; ck < NCHUNKS; ++ck) {
        cp_wait<0>();          // chunk ck's data (and csq on ck==0) landed
        __syncthreads();       // visibility + all warps done with buf (ck+1)&1

        if (ck + 1 < NCHUNKS) {
            const char* src = reinterpret_cast<const char*>(g_Bfrag)
                              + (ck + 1) * CHUNK_BYTES;
            const uint32_t dst = sbase + SM_BB + ((ck + 1) & 1) * CHUNK_BYTES;
            #pragma unroll
            for (int i = 0; i < 8; ++i) {
                const int off = (i * 128 + tid) * 16;
                cp16(dst + off, src + off);
            }
            cp_commit();
        }

        const char* bb = smem + SM_BB + (ck & 1) * CHUNK_BYTES;
        #pragma unroll
        for (int g = 0; g < 2; ++g) {       // 2 nb-groups -> only 16 live accs
            float acc[2][2][4];
            #pragma unroll
            for (int mt = 0; mt < 2; ++mt)
                #pragma unroll
                for (int nbl = 0; nbl < 2; ++nbl)
                    #pragma unroll
                    for (int c = 0; c < 4; ++c) acc[mt][nbl][c] = 0.0f;

            #pragma unroll
            for (int ks = 0; ks < 16; ++ks) {
                #pragma unroll
                for (int nbl = 0; nbl < 2; ++nbl) {
                    const int nb = g * 2 + nbl;
                    const uint2 b = *reinterpret_cast<const uint2*>(
                        bb + ((nb * 16 + ks) * 32 + l) * 8);
                    mma16816(acc[0][nbl], a[0][ks], b.x, b.y);
                    mma16816(acc[1][nbl], a[1][ks], b.x, b.y);
                }
            }
            // fold (csq - 2*dot) into running min
            #pragma unroll
            for (int nbl = 0; nbl < 2; ++nbl) {
                const int col = ck * NCH + (g * 2 + nbl) * 8 + 2 * (l & 3);
                const float cq0 = csq_s[col];
                const float cq1 = csq_s[col + 1];
                #pragma unroll
                for (int mt = 0; mt < 2; ++mt) {
                    const float v0 = fminf(fmaf(-2.0f, acc[mt][nbl][0], cq0),
                                           fmaf(-2.0f, acc[mt][nbl][1], cq1));
                    const float v1 = fminf(fmaf(-2.0f, acc[mt][nbl][2], cq0),
                                           fmaf(-2.0f, acc[mt][nbl][3], cq1));
                    minv[mt][0] = fminf(minv[mt][0], v0);
                    minv[mt][1] = fminf(minv[mt][1], v1);
                }
            }
        }
        // no trailing barrier: next iteration's post-wait barrier protects
        // buffer reuse (cp for ck+2 is issued only after it).
    }

    // ---- epilogue: per-row min -> sqrt -> deterministic partial sum ----
    float s = 0.0f;
    #pragma unroll
    for (int mt = 0; mt < 2; ++mt) {
        #pragma unroll
        for (int h = 0; h < 2; ++h) {
            float m = minv[mt][h];
            m = fminf(m, __shfl_xor_sync(0xFFFFFFFFu, m, 1));
            m = fminf(m, __shfl_xor_sync(0xFFFFFFFFu, m, 2));
            const float d = sqrtf(fmaxf(xs[mt][h] + m, 0.0f));
            if ((l & 3) == 0) s += d;
        }
    }
    #pragma unroll
    for (int off = 16; off; off >>= 1) s += __shfl_down_sync(0xFFFFFFFFu, s, off);
    if (l == 0) red_s[w] = s;
    __syncthreads();

    __shared__ unsigned int is_last;
    if (tid == 0) {
        g_partials[blockIdx.x] = (red_s[0] + red_s[1]) + (red_s[2] + red_s[3]);
        __threadfence();
        const unsigned int prev = atomicAdd(&g_done, 1u);
        is_last = (prev == (unsigned)(NUM_CTAS - 1)) ? 1u : 0u;
    }
    __syncthreads();

    if (is_last) {
        __threadfence();
        float v = g_partials[tid] + g_partials[tid + 128]
                + g_partials[tid + 256] + g_partials[tid + 384];
        #pragma unroll
        for (int off = 16; off; off >>= 1) v += __shfl_down_sync(0xFFFFFFFFu, v, off);
        if (l == 0) red_s[w] = v;
        __syncthreads();
        if (tid == 0) {
            const float t = (red_s[0] + red_s[1]) + (red_s[2] + red_s[3]);
            out[0] = t * (ALPHA / (float)BATCH);
            g_done = 0u;                 // reset for next graph replay
            __threadfence();
        }
    }
}

} // namespace km

extern "C" void kernel_launch(void* const* d_in, const int* in_sizes, int n_in,
                              void* d_out, int out_size) {
    const float* emb = (const float*)d_in[0];   // [65536, 256] fp32
    const float* ctr = (const float*)d_in[1];   // [512, 256]  fp32
    float* out = (float*)d_out;                 // scalar fp32

    cudaFuncSetAttribute(km::kmeans_main,
                         cudaFuncAttributeMaxDynamicSharedMemorySize, km::SMEM_TOTAL);

    km::convert_centers<<<16, 128>>>(ctr);
    km::kmeans_main<<<km::NUM_CTAS, 128, km::SMEM_TOTAL>>>(emb, out);
}

// round 5
// speedup vs baseline: 1.0908x; 1.0908x over previous
#include <cuda_runtime.h>
#include <cuda_bf16.h>
#include <cstdint>
#include <cstddef>

// ============================================================================
// KMeansLoss on GB300 via legacy mma.sync (HMMA bf16) — harness ptxas target
// is sm_103 (no 'a'); tcgen05 unavailable.
//
// loss = ALPHA * mean_n sqrt(max( xsq[n] + min_k( csq[k] - 2*dot(x_n,c_k) ), 0))
//
// Kernel 0 (64 CTAs x 32 thr): centers fp32 -> bf16 fragment order + exact csq.
// Kernel 1 (512 CTAs x 128 thr, 2 CTAs/SM): warp owns 32 rows (2 m16 tiles);
//   A fragments loaded directly gmem->regs (128 regs) + exact fp32 xsq in regs;
//   16 N-chunks of 32 centers: cp.async double-buffered B in smem, B fragments
//   double-buffered in REGISTERS one ks ahead (hides 29cyc LDS latency),
//   8 independent HMMA chains per ks (full 32-float acc), fold (csq - 2*dot)
//   into running per-row min; deterministic last-CTA reduction -> scalar.
// ============================================================================

namespace km {

constexpr int BATCH = 65536;
constexpr int KC    = 512;
constexpr int DIM   = 256;
constexpr float ALPHA = 0.05f;

constexpr int M_CTA    = 128;
constexpr int NUM_CTAS = BATCH / M_CTA;     // 512
constexpr int NCH      = 32;                // centers per chunk
constexpr int NCHUNKS  = KC / NCH;          // 16
constexpr int CHUNK_BYTES = NCH * DIM * 2;  // 16384

// ---- dynamic smem layout ----
constexpr int SM_CSQ = 0;                   // 512 f = 2048 B
constexpr int SM_RED = 2048;                // 4 f
constexpr int SM_BB  = 4096;                // 2 x 16 KB B buffers
constexpr int SMEM_TOTAL = SM_BB + 2 * CHUNK_BYTES;   // 36864

// B fragments: [nbg(64)][ks(16)][lane(32)] x uint2 (b0 = k pair, b1 = k+8 pair)
__device__ uint2 g_Bfrag[(KC / 8) * 16 * 32];
__device__ float g_csq[KC];
__device__ float g_partials[NUM_CTAS];
__device__ unsigned int g_done;

// ---------------------------- helpers ---------------------------------------
__device__ __forceinline__ uint32_t pk_bf16x2(float lo, float hi) {
    uint32_t r;
    asm("cvt.rn.bf16x2.f32 %0, %1, %2;" : "=r"(r) : "f"(hi), "f"(lo));
    return r;
}
__device__ __forceinline__ void mma16816(float c[4], const uint32_t a[4],
                                         uint32_t b0, uint32_t b1) {
    asm volatile(
        "mma.sync.aligned.m16n8k16.row.col.f32.bf16.bf16.f32 "
        "{%0,%1,%2,%3}, {%4,%5,%6,%7}, {%8,%9}, {%0,%1,%2,%3};"
        : "+f"(c[0]), "+f"(c[1]), "+f"(c[2]), "+f"(c[3])
        : "r"(a[0]), "r"(a[1]), "r"(a[2]), "r"(a[3]), "r"(b0), "r"(b1));
}
__device__ __forceinline__ uint32_t smem_u32(const void* p) {
    return (uint32_t)__cvta_generic_to_shared(p);
}
__device__ __forceinline__ void cp16(uint32_t sdst, const void* gsrc) {
    asm volatile("cp.async.cg.shared.global [%0], [%1], 16;"
                 :: "r"(sdst), "l"(gsrc) : "memory");
}
__device__ __forceinline__ void cp_commit() {
    asm volatile("cp.async.commit_group;" ::: "memory");
}
template <int N>
__device__ __forceinline__ void cp_wait() {
    asm volatile("cp.async.wait_group %0;" :: "n"(N) : "memory");
}

// ------------------------- kernel 0: center convert -------------------------
// 64 CTAs x 32 thr: one warp per 8-center fragment group (nbg).
__global__ void __launch_bounds__(32) convert_centers(const float* __restrict__ ctr) {
    const int l   = threadIdx.x & 31;
    const int nbg = blockIdx.x;                 // 0..63
    const int n   = nbg * 8 + (l >> 2);
    const float* row = ctr + (size_t)n * DIM;
    float cs = 0.0f;
    #pragma unroll
    for (int ks = 0; ks < 16; ++ks) {
        const int k0 = ks * 16 + 2 * (l & 3);
        const float2 v0 = *reinterpret_cast<const float2*>(row + k0);
        const float2 v1 = *reinterpret_cast<const float2*>(row + k0 + 8);
        cs = fmaf(v0.x, v0.x, cs); cs = fmaf(v0.y, v0.y, cs);
        cs = fmaf(v1.x, v1.x, cs); cs = fmaf(v1.y, v1.y, cs);
        uint2 u;
        u.x = pk_bf16x2(v0.x, v0.y);
        u.y = pk_bf16x2(v1.x, v1.y);
        g_Bfrag[(nbg * 16 + ks) * 32 + l] = u;
    }
    cs += __shfl_xor_sync(0xFFFFFFFFu, cs, 1);
    cs += __shfl_xor_sync(0xFFFFFFFFu, cs, 2);
    if ((l & 3) == 0) g_csq[n] = cs;
}

// ------------------------- kernel 1: main GEMM+min --------------------------
__global__ void __launch_bounds__(128, 2)
kmeans_main(const float* __restrict__ emb, float* __restrict__ out) {
    extern __shared__ char smem[];
    const int tid = threadIdx.x;
    const int w   = tid >> 5;        // warp 0..3
    const int l   = tid & 31;
    const int m0  = blockIdx.x * M_CTA;
    float* csq_s = reinterpret_cast<float*>(smem + SM_CSQ);
    float* red_s = reinterpret_cast<float*>(smem + SM_RED);
    const uint32_t sbase = smem_u32(smem);

    // ---- prefetch csq + B chunk 0 (overlaps the whole A prologue) ----
    cp16(sbase + SM_CSQ + tid * 16,
         reinterpret_cast<const char*>(g_csq) + tid * 16);
    {
        const char* src = reinterpret_cast<const char*>(g_Bfrag);
        #pragma unroll
        for (int i = 0; i < 8; ++i) {
            const int off = (i * 128 + tid) * 16;
            cp16(sbase + SM_BB + off, src + off);
        }
    }
    cp_commit();

    // ---- A prologue: direct gmem -> register fragments, fused exact xsq ----
    uint32_t a[2][16][4];
    float xs[2][2];
    xs[0][0] = 0.0f; xs[0][1] = 0.0f; xs[1][0] = 0.0f; xs[1][1] = 0.0f;
    {
        const float* base = emb + (size_t)(m0 + w * 32 + (l >> 2)) * DIM + 2 * (l & 3);
        #pragma unroll
        for (int mt = 0; mt < 2; ++mt) {
            const float* p0 = base + (size_t)(mt * 16) * DIM;
            const float* p8 = p0 + (size_t)8 * DIM;
            #pragma unroll
            for (int ks = 0; ks < 16; ++ks) {
                const float2 v00 = *reinterpret_cast<const float2*>(p0 + ks * 16);
                const float2 v01 = *reinterpret_cast<const float2*>(p0 + ks * 16 + 8);
                const float2 v10 = *reinterpret_cast<const float2*>(p8 + ks * 16);
                const float2 v11 = *reinterpret_cast<const float2*>(p8 + ks * 16 + 8);
                xs[mt][0] = fmaf(v00.x, v00.x, xs[mt][0]);
                xs[mt][0] = fmaf(v00.y, v00.y, xs[mt][0]);
                xs[mt][0] = fmaf(v01.x, v01.x, xs[mt][0]);
                xs[mt][0] = fmaf(v01.y, v01.y, xs[mt][0]);
                xs[mt][1] = fmaf(v10.x, v10.x, xs[mt][1]);
                xs[mt][1] = fmaf(v10.y, v10.y, xs[mt][1]);
                xs[mt][1] = fmaf(v11.x, v11.x, xs[mt][1]);
                xs[mt][1] = fmaf(v11.y, v11.y, xs[mt][1]);
                a[mt][ks][0] = pk_bf16x2(v00.x, v00.y);
                a[mt][ks][1] = pk_bf16x2(v10.x, v10.y);
                a[mt][ks][2] = pk_bf16x2(v01.x, v01.y);
                a[mt][ks][3] = pk_bf16x2(v11.x, v11.y);
            }
        }
    }
    #pragma unroll
    for (int mt = 0; mt < 2; ++mt) {
        #pragma unroll
        for (int h = 0; h < 2; ++h) {
            xs[mt][h] += __shfl_xor_sync(0xFFFFFFFFu, xs[mt][h], 1);
            xs[mt][h] += __shfl_xor_sync(0xFFFFFFFFu, xs[mt][h], 2);
        }
    }

    float minv[2][2];
    minv[0][0] = 3.4e38f; minv[0][1] = 3.4e38f;
    minv[1][0] = 3.4e38f; minv[1][1] = 3.4e38f;

    // ---- mainloop: 16 chunks of 32 centers ----
    #pragma unroll 1
    for (int ck = 0; ck < NCHUNKS; ++ck) {
        if (ck + 1 < NCHUNKS) {
            const char* src = reinterpret_cast<const char*>(g_Bfrag)
                              + (ck + 1) * CHUNK_BYTES;
            const uint32_t dst = sbase + SM_BB + ((ck + 1) & 1) * CHUNK_BYTES;
            #pragma unroll
            for (int i = 0; i < 8; ++i) {
                const int off = (i * 128 + tid) * 16;
                cp16(dst + off, src + off);
            }
            cp_commit();
            cp_wait<1>();          // chunk ck's data landed
        } else {
            cp_wait<0>();
        }
        __syncthreads();

        float acc[2][4][4];
        #pragma unroll
        for (int mt = 0; mt < 2; ++mt)
            #pragma unroll
            for (int nb = 0; nb < 4; ++nb)
                #pragma unroll
                for (int c = 0; c < 4; ++c) acc[mt][nb][c] = 0.0f;

        const char* bb = smem + SM_BB + (ck & 1) * CHUNK_BYTES;

        // B fragments double-buffered in registers, one ks ahead
        uint2 breg[2][4];
        #pragma unroll
        for (int nb = 0; nb < 4; ++nb)
            breg[0][nb] = *reinterpret_cast<const uint2*>(
                bb + ((nb * 16 + 0) * 32 + l) * 8);

        #pragma unroll
        for (int ks = 0; ks < 16; ++ks) {
            const int cur = ks & 1, nxt = cur ^ 1;
            if (ks + 1 < 16) {
                #pragma unroll
                for (int nb = 0; nb < 4; ++nb)
                    breg[nxt][nb] = *reinterpret_cast<const uint2*>(
                        bb + ((nb * 16 + ks + 1) * 32 + l) * 8);
            }
            #pragma unroll
            for (int nb = 0; nb < 4; ++nb) {
                mma16816(acc[0][nb], a[0][ks], breg[cur][nb].x, breg[cur][nb].y);
                mma16816(acc[1][nb], a[1][ks], breg[cur][nb].x, breg[cur][nb].y);
            }
        }

        // fold (csq - 2*dot) into running min
        #pragma unroll
        for (int nb = 0; nb < 4; ++nb) {
            const int col = ck * NCH + nb * 8 + 2 * (l & 3);
            const float cq0 = csq_s[col];
            const float cq1 = csq_s[col + 1];
            #pragma unroll
            for (int mt = 0; mt < 2; ++mt) {
                const float v0 = fminf(fmaf(-2.0f, acc[mt][nb][0], cq0),
                                       fmaf(-2.0f, acc[mt][nb][1], cq1));
                const float v1 = fminf(fmaf(-2.0f, acc[mt][nb][2], cq0),
                                       fmaf(-2.0f, acc[mt][nb][3], cq1));
                minv[mt][0] = fminf(minv[mt][0], v0);
                minv[mt][1] = fminf(minv[mt][1], v1);
            }
        }
        __syncthreads();   // all warps done with buf (ck&1) before refill
    }

    // ---- epilogue: per-row min -> sqrt -> deterministic partial sum ----
    float s = 0.0f;
    #pragma unroll
    for (int mt = 0; mt < 2; ++mt) {
        #pragma unroll
        for (int h = 0; h < 2; ++h) {
            float m = minv[mt][h];
            m = fminf(m, __shfl_xor_sync(0xFFFFFFFFu, m, 1));
            m = fminf(m, __shfl_xor_sync(0xFFFFFFFFu, m, 2));
            const float d = sqrtf(fmaxf(xs[mt][h] + m, 0.0f));
            if ((l & 3) == 0) s += d;
        }
    }
    #pragma unroll
    for (int off = 16; off; off >>= 1) s += __shfl_down_sync(0xFFFFFFFFu, s, off);
    if (l == 0) red_s[w] = s;
    __syncthreads();

    __shared__ unsigned int is_last;
    if (tid == 0) {
        g_partials[blockIdx.x] = (red_s[0] + red_s[1]) + (red_s[2] + red_s[3]);
        __threadfence();
        const unsigned int prev = atomicAdd(&g_done, 1u);
        is_last = (prev == (unsigned)(NUM_CTAS - 1)) ? 1u : 0u;
    }
    __syncthreads();

    if (is_last) {
        __threadfence();
        float v = g_partials[tid] + g_partials[tid + 128]
                + g_partials[tid + 256] + g_partials[tid + 384];
        #pragma unroll
        for (int off = 16; off; off >>= 1) v += __shfl_down_sync(0xFFFFFFFFu, v, off);
        if (l == 0) red_s[w] = v;
        __syncthreads();
        if (tid == 0) {
            const float t = (red_s[0] + red_s[1]) + (red_s[2] + red_s[3]);
            out[0] = t * (ALPHA / (float)BATCH);
            g_done = 0u;                 // reset for next graph replay
            __threadfence();
        }
    }
}

} // namespace km

extern "C" void kernel_launch(void* const* d_in, const int* in_sizes, int n_in,
                              void* d_out, int out_size) {
    const float* emb = (const float*)d_in[0];   // [65536, 256] fp32
    const float* ctr = (const float*)d_in[1];   // [512, 256]  fp32
    float* out = (float*)d_out;                 // scalar fp32

    cudaFuncSetAttribute(km::kmeans_main,
                         cudaFuncAttributeMaxDynamicSharedMemorySize, km::SMEM_TOTAL);

    km::convert_centers<<<64, 32>>>(ctr);
    km::kmeans_main<<<km::NUM_CTAS, 128, km::SMEM_TOTAL>>>(emb, out);
}

// round 6
// speedup vs baseline: 1.2028x; 1.1027x over previous
#include <cuda_runtime.h>
#include <cuda_bf16.h>
#include <cstdint>
#include <cstddef>

// ============================================================================
// KMeansLoss on GB300 via legacy mma.sync (HMMA bf16) — harness ptxas target
// is sm_103 (no 'a'); tcgen05 unavailable.
//
// loss = ALPHA * mean_n sqrt(max( xsq[n] + min_k( csq[k] - 2*dot(x_n,c_k) ), 0))
//
// Kernel 0 (64 CTAs x 32 thr): centers fp32 -> bf16 fragment order + exact csq.
// Kernel 1 (512 CTAs x 128 thr, 2 CTAs/SM): warp owns 32 rows (2 m16 tiles);
//   A fragments direct gmem->regs (128 regs) + exact fp32 xsq in regs.
//   B streamed through a 6-STAGE MBARRIER PIPELINE (produce distance 3,
//   cp.async.mbarrier.arrive.noinc) — ZERO __syncthreads in the mainloop,
//   warps free-run with up to +-3 chunks of skew. 8 independent HMMA chains
//   per ks. Fold (csq - 2*dot) into running per-row min.
//   Deterministic last-CTA reduction -> scalar.
// ============================================================================

namespace km {

constexpr int BATCH = 65536;
constexpr int KC    = 512;
constexpr int DIM   = 256;
constexpr float ALPHA = 0.05f;

constexpr int M_CTA    = 128;
constexpr int NUM_CTAS = BATCH / M_CTA;     // 512
constexpr int NCH      = 32;                // centers per chunk
constexpr int NCHUNKS  = KC / NCH;          // 16
constexpr int CHUNK_BYTES = NCH * DIM * 2;  // 16384
constexpr int NSTAGE   = 6;                 // pipeline stages
constexpr int PDIST    = 3;                 // produce distance (<= NSTAGE-3 skew)

// ---- dynamic smem layout ----
constexpr int SM_CSQ  = 0;                  // 512 f = 2048 B
constexpr int SM_RED  = 2048;               // 4 f
constexpr int SM_MBF  = 2112;               // full mbars, 6 x 8B
constexpr int SM_MBE  = 2176;               // empty mbars, 6 x 8B
constexpr int SM_BB   = 4096;               // 6 x 16 KB B stages
constexpr int SMEM_TOTAL = SM_BB + NSTAGE * CHUNK_BYTES;   // 102400 (2 CTAs/SM)

// B fragments: [nbg(64)][ks(16)][lane(32)] x uint2 (b0 = k pair, b1 = k+8 pair)
__device__ uint2 g_Bfrag[(KC / 8) * 16 * 32];
__device__ float g_csq[KC];
__device__ float g_partials[NUM_CTAS];
__device__ unsigned int g_done;

// ---------------------------- helpers ---------------------------------------
__device__ __forceinline__ uint32_t pk_bf16x2(float lo, float hi) {
    uint32_t r;
    asm("cvt.rn.bf16x2.f32 %0, %1, %2;" : "=r"(r) : "f"(hi), "f"(lo));
    return r;
}
__device__ __forceinline__ void mma16816(float c[4], const uint32_t a[4],
                                         uint32_t b0, uint32_t b1) {
    asm volatile(
        "mma.sync.aligned.m16n8k16.row.col.f32.bf16.bf16.f32 "
        "{%0,%1,%2,%3}, {%4,%5,%6,%7}, {%8,%9}, {%0,%1,%2,%3};"
        : "+f"(c[0]), "+f"(c[1]), "+f"(c[2]), "+f"(c[3])
        : "r"(a[0]), "r"(a[1]), "r"(a[2]), "r"(a[3]), "r"(b0), "r"(b1));
}
__device__ __forceinline__ uint32_t smem_u32(const void* p) {
    return (uint32_t)__cvta_generic_to_shared(p);
}
__device__ __forceinline__ void cp16(uint32_t sdst, const void* gsrc) {
    asm volatile("cp.async.cg.shared.global [%0], [%1], 16;"
                 :: "r"(sdst), "l"(gsrc) : "memory");
}
__device__ __forceinline__ void cp_mbar_arrive_noinc(uint32_t mbar) {
    asm volatile("cp.async.mbarrier.arrive.noinc.shared::cta.b64 [%0];"
                 :: "r"(mbar) : "memory");
}
__device__ __forceinline__ void mbar_init(uint32_t a, uint32_t cnt) {
    asm volatile("mbarrier.init.shared.b64 [%0], %1;" :: "r"(a), "r"(cnt) : "memory");
}
__device__ __forceinline__ void mbar_arrive(uint32_t a) {
    asm volatile("mbarrier.arrive.shared.b64 _, [%0];" :: "r"(a) : "memory");
}
__device__ __forceinline__ void mbar_wait_parity(uint32_t mbar, uint32_t phase) {
    uint32_t done;
    do {
        asm volatile("{\n .reg .pred p;\n"
                     " mbarrier.try_wait.parity.acquire.cta.shared::cta.b64 p, [%1], %2, 0x989680;\n"
                     " selp.b32 %0, 1, 0, p;\n}"
                     : "=r"(done) : "r"(mbar), "r"(phase) : "memory");
    } while (!done);
}

// ------------------------- kernel 0: center convert -------------------------
__global__ void __launch_bounds__(32) convert_centers(const float* __restrict__ ctr) {
    const int l   = threadIdx.x & 31;
    const int nbg = blockIdx.x;                 // 0..63
    const int n   = nbg * 8 + (l >> 2);
    const float* row = ctr + (size_t)n * DIM;
    float cs = 0.0f;
    #pragma unroll
    for (int ks = 0; ks < 16; ++ks) {
        const int k0 = ks * 16 + 2 * (l & 3);
        const float2 v0 = *reinterpret_cast<const float2*>(row + k0);
        const float2 v1 = *reinterpret_cast<const float2*>(row + k0 + 8);
        cs = fmaf(v0.x, v0.x, cs); cs = fmaf(v0.y, v0.y, cs);
        cs = fmaf(v1.x, v1.x, cs); cs = fmaf(v1.y, v1.y, cs);
        uint2 u;
        u.x = pk_bf16x2(v0.x, v0.y);
        u.y = pk_bf16x2(v1.x, v1.y);
        g_Bfrag[(nbg * 16 + ks) * 32 + l] = u;
    }
    cs += __shfl_xor_sync(0xFFFFFFFFu, cs, 1);
    cs += __shfl_xor_sync(0xFFFFFFFFu, cs, 2);
    if ((l & 3) == 0) g_csq[n] = cs;
}

// ------------------------- kernel 1: main GEMM+min --------------------------
__global__ void __launch_bounds__(128, 2)
kmeans_main(const float* __restrict__ emb, float* __restrict__ out) {
    extern __shared__ char smem[];
    const int tid = threadIdx.x;
    const int w   = tid >> 5;        // warp 0..3
    const int l   = tid & 31;
    const int m0  = blockIdx.x * M_CTA;
    float* csq_s = reinterpret_cast<float*>(smem + SM_CSQ);
    float* red_s = reinterpret_cast<float*>(smem + SM_RED);
    const uint32_t sbase = smem_u32(smem);

    // ---- init pipeline mbarriers + stage csq in smem ----
    if (tid == 0) {
        #pragma unroll
        for (int s = 0; s < NSTAGE; ++s) {
            mbar_init(sbase + SM_MBF + s * 8, 128);   // full: 128 noinc cp arrivals
            mbar_init(sbase + SM_MBE + s * 8, 128);   // empty: 128 thread arrivals
        }
    }
    reinterpret_cast<float4*>(csq_s)[tid] =
        reinterpret_cast<const float4*>(g_csq)[tid];
    __syncthreads();   // mbars + csq visible to all warps

    // ---- prefill stages 0..PDIST-1 with chunks 0..PDIST-1 ----
    #pragma unroll
    for (int s = 0; s < PDIST; ++s) {
        const char* src = reinterpret_cast<const char*>(g_Bfrag) + s * CHUNK_BYTES;
        const uint32_t dst = sbase + SM_BB + s * CHUNK_BYTES;
        #pragma unroll
        for (int i = 0; i < 8; ++i) {
            const int off = (i * 128 + tid) * 16;
            cp16(dst + off, src + off);
        }
        cp_mbar_arrive_noinc(sbase + SM_MBF + s * 8);
    }

    // ---- A prologue: direct gmem -> register fragments, fused exact xsq ----
    uint32_t a[2][16][4];
    float xs[2][2];
    xs[0][0] = 0.0f; xs[0][1] = 0.0f; xs[1][0] = 0.0f; xs[1][1] = 0.0f;
    {
        const float* base = emb + (size_t)(m0 + w * 32 + (l >> 2)) * DIM + 2 * (l & 3);
        #pragma unroll
        for (int mt = 0; mt < 2; ++mt) {
            const float* p0 = base + (size_t)(mt * 16) * DIM;
            const float* p8 = p0 + (size_t)8 * DIM;
            #pragma unroll
            for (int ks = 0; ks < 16; ++ks) {
                const float2 v00 = *reinterpret_cast<const float2*>(p0 + ks * 16);
                const float2 v01 = *reinterpret_cast<const float2*>(p0 + ks * 16 + 8);
                const float2 v10 = *reinterpret_cast<const float2*>(p8 + ks * 16);
                const float2 v11 = *reinterpret_cast<const float2*>(p8 + ks * 16 + 8);
                xs[mt][0] = fmaf(v00.x, v00.x, xs[mt][0]);
                xs[mt][0] = fmaf(v00.y, v00.y, xs[mt][0]);
                xs[mt][0] = fmaf(v01.x, v01.x, xs[mt][0]);
                xs[mt][0] = fmaf(v01.y, v01.y, xs[mt][0]);
                xs[mt][1] = fmaf(v10.x, v10.x, xs[mt][1]);
                xs[mt][1] = fmaf(v10.y, v10.y, xs[mt][1]);
                xs[mt][1] = fmaf(v11.x, v11.x, xs[mt][1]);
                xs[mt][1] = fmaf(v11.y, v11.y, xs[mt][1]);
                a[mt][ks][0] = pk_bf16x2(v00.x, v00.y);
                a[mt][ks][1] = pk_bf16x2(v10.x, v10.y);
                a[mt][ks][2] = pk_bf16x2(v01.x, v01.y);
                a[mt][ks][3] = pk_bf16x2(v11.x, v11.y);
            }
        }
    }
    #pragma unroll
    for (int mt = 0; mt < 2; ++mt) {
        #pragma unroll
        for (int h = 0; h < 2; ++h) {
            xs[mt][h] += __shfl_xor_sync(0xFFFFFFFFu, xs[mt][h], 1);
            xs[mt][h] += __shfl_xor_sync(0xFFFFFFFFu, xs[mt][h], 2);
        }
    }

    float minv[2][2];
    minv[0][0] = 3.4e38f; minv[0][1] = 3.4e38f;
    minv[1][0] = 3.4e38f; minv[1][1] = 3.4e38f;

    // ---- mainloop: 16 chunks, mbarrier pipeline, NO __syncthreads ----
    int cst = 0, cph = 0;        // consume stage / full-phase
    int pst = PDIST, pph = 1;    // produce stage / empty-phase (flips to 0 at first wrap)

    #pragma unroll 1
    for (int ck = 0; ck < NCHUNKS; ++ck) {
        // consume: wait chunk ck's data
        mbar_wait_parity(sbase + SM_MBF + cst * 8, (uint32_t)cph);

        const char* bb = smem + SM_BB + cst * CHUNK_BYTES;

        float acc[2][4][4];
        #pragma unroll
        for (int mt = 0; mt < 2; ++mt)
            #pragma unroll
            for (int nb = 0; nb < 4; ++nb)
                #pragma unroll
                for (int c = 0; c < 4; ++c) acc[mt][nb][c] = 0.0f;

        uint2 breg[2][4];
        #pragma unroll
        for (int nb = 0; nb < 4; ++nb)
            breg[0][nb] = *reinterpret_cast<const uint2*>(
                bb + ((nb * 16 + 0) * 32 + l) * 8);

        #pragma unroll
        for (int ks = 0; ks < 16; ++ks) {
            const int cur = ks & 1, nxt = cur ^ 1;
            if (ks + 1 < 16) {
                #pragma unroll
                for (int nb = 0; nb < 4; ++nb)
                    breg[nxt][nb] = *reinterpret_cast<const uint2*>(
                        bb + ((nb * 16 + ks + 1) * 32 + l) * 8);
            }
            #pragma unroll
            for (int nb = 0; nb < 4; ++nb) {
                mma16816(acc[0][nb], a[0][ks], breg[cur][nb].x, breg[cur][nb].y);
                mma16816(acc[1][nb], a[1][ks], breg[cur][nb].x, breg[cur][nb].y);
            }
        }

        // done reading this stage
        mbar_arrive(sbase + SM_MBE + cst * 8);

        // produce chunk ck+PDIST into its stage (wait empty only if stage was used)
        const int cp = ck + PDIST;
        if (cp < NCHUNKS) {
            if (cp >= NSTAGE)
                mbar_wait_parity(sbase + SM_MBE + pst * 8, (uint32_t)pph);
            const char* src = reinterpret_cast<const char*>(g_Bfrag)
                              + cp * CHUNK_BYTES;
            const uint32_t dst = sbase + SM_BB + pst * CHUNK_BYTES;
            #pragma unroll
            for (int i = 0; i < 8; ++i) {
                const int off = (i * 128 + tid) * 16;
                cp16(dst + off, src + off);
            }
            cp_mbar_arrive_noinc(sbase + SM_MBF + pst * 8);
            if (++pst == NSTAGE) { pst = 0; pph ^= 1; }
        }

        // fold (csq - 2*dot) into running min (off the critical smem path)
        #pragma unroll
        for (int nb = 0; nb < 4; ++nb) {
            const int col = ck * NCH + nb * 8 + 2 * (l & 3);
            const float cq0 = csq_s[col];
            const float cq1 = csq_s[col + 1];
            #pragma unroll
            for (int mt = 0; mt < 2; ++mt) {
                const float v0 = fminf(fmaf(-2.0f, acc[mt][nb][0], cq0),
                                       fmaf(-2.0f, acc[mt][nb][1], cq1));
                const float v1 = fminf(fmaf(-2.0f, acc[mt][nb][2], cq0),
                                       fmaf(-2.0f, acc[mt][nb][3], cq1));
                minv[mt][0] = fminf(minv[mt][0], v0);
                minv[mt][1] = fminf(minv[mt][1], v1);
            }
        }

        if (++cst == NSTAGE) { cst = 0; cph ^= 1; }
    }

    // ---- epilogue: per-row min -> sqrt -> deterministic partial sum ----
    float s = 0.0f;
    #pragma unroll
    for (int mt = 0; mt < 2; ++mt) {
        #pragma unroll
        for (int h = 0; h < 2; ++h) {
            float m = minv[mt][h];
            m = fminf(m, __shfl_xor_sync(0xFFFFFFFFu, m, 1));
            m = fminf(m, __shfl_xor_sync(0xFFFFFFFFu, m, 2));
            const float d = sqrtf(fmaxf(xs[mt][h] + m, 0.0f));
            if ((l & 3) == 0) s += d;
        }
    }
    #pragma unroll
    for (int off = 16; off; off >>= 1) s += __shfl_down_sync(0xFFFFFFFFu, s, off);
    if (l == 0) red_s[w] = s;
    __syncthreads();

    __shared__ unsigned int is_last;
    if (tid == 0) {
        g_partials[blockIdx.x] = (red_s[0] + red_s[1]) + (red_s[2] + red_s[3]);
        __threadfence();
        const unsigned int prev = atomicAdd(&g_done, 1u);
        is_last = (prev == (unsigned)(NUM_CTAS - 1)) ? 1u : 0u;
    }
    __syncthreads();

    if (is_last) {
        __threadfence();
        float v = g_partials[tid] + g_partials[tid + 128]
                + g_partials[tid + 256] + g_partials[tid + 384];
        #pragma unroll
        for (int off = 16; off; off >>= 1) v += __shfl_down_sync(0xFFFFFFFFu, v, off);
        if (l == 0) red_s[w] = v;
        __syncthreads();
        if (tid == 0) {
            const float t = (red_s[0] + red_s[1]) + (red_s[2] + red_s[3]);
            out[0] = t * (ALPHA / (float)BATCH);
            g_done = 0u;                 // reset for next graph replay
            __threadfence();
        }
    }
}

} // namespace km

extern "C" void kernel_launch(void* const* d_in, const int* in_sizes, int n_in,
                              void* d_out, int out_size) {
    const float* emb = (const float*)d_in[0];   // [65536, 256] fp32
    const float* ctr = (const float*)d_in[1];   // [512, 256]  fp32
    float* out = (float*)d_out;                 // scalar fp32

    cudaFuncSetAttribute(km::kmeans_main,
                         cudaFuncAttributeMaxDynamicSharedMemorySize, km::SMEM_TOTAL);

    km::convert_centers<<<64, 32>>>(ctr);
    km::kmeans_main<<<km::NUM_CTAS, 128, km::SMEM_TOTAL>>>(emb, out);
}